// round 11
// baseline (speedup 1.0000x reference)
#include <cuda_runtime.h>
#include <math.h>

#define EPS 1e-5f

// ---------------- scratch (device globals; no allocation allowed) ----------------
__device__ float g_bufA [2*256*64*64];     // inorm(x)
__device__ float g_bufB [2*128*64*64];     // conv_down out
__device__ float g_bufC [2*128*64*64];     // mid + residual
__device__ float g_bufG2[2*128*128*128];   // adjust_ef_lv2
__device__ float g_bufK2[2*9*128*128];     // pac kernel lvl2
__device__ float g_bufX16[2*64*128*128];   // layer16 out (and norm rounds, in place)
__device__ float g_bufG1[2*64*256*256];    // adjust_ef_lv1
__device__ float g_bufK1[2*9*256*256];     // pac kernel lvl1
__device__ float g_bufX20[2*32*256*256];   // layer20 out
__device__ float g_stats[2*256*2];         // per-(b,c) {mean,rstd} or {A,mB}

// ---------------- helpers ----------------
__device__ __forceinline__ float warp_sum(float v) {
#pragma unroll
    for (int off = 16; off > 0; off >>= 1)
        v += __shfl_xor_sync(0xFFFFFFFFu, v, off);
    return v;
}

// ---------------- instance norm stats (single round: stores mean, rstd) ----------------
__global__ void inorm_stats_kernel(const float* __restrict__ x, float* __restrict__ stats, int HW) {
    int bc = blockIdx.x;
    const float4* p = (const float4*)(x + (size_t)bc * HW);
    int n4 = HW >> 2;
    __shared__ float red[8];
    __shared__ float mean_s;
    int wid = threadIdx.x >> 5, lid = threadIdx.x & 31;

    float s = 0.f;
    for (int i = threadIdx.x; i < n4; i += 256) {
        float4 v = p[i];
        s += v.x + v.y + v.z + v.w;
    }
    s = warp_sum(s);
    if (lid == 0) red[wid] = s;
    __syncthreads();
    if (threadIdx.x == 0) {
        float tot = 0.f;
#pragma unroll
        for (int i = 0; i < 8; i++) tot += red[i];
        mean_s = tot / (float)HW;
    }
    __syncthreads();

    float m = mean_s;
    float vs = 0.f;
    for (int i = threadIdx.x; i < n4; i += 256) {
        float4 v = p[i];
        float d0 = v.x - m, d1 = v.y - m, d2 = v.z - m, d3 = v.w - m;
        vs += d0*d0 + d1*d1 + d2*d2 + d3*d3;
    }
    vs = warp_sum(vs);
    if (lid == 0) red[wid] = vs;
    __syncthreads();
    if (threadIdx.x == 0) {
        float tot = 0.f;
#pragma unroll
        for (int i = 0; i < 8; i++) tot += red[i];
        stats[2*bc]   = m;
        stats[2*bc+1] = rsqrtf(tot / (float)HW + EPS);
    }
}

// ---------------- fused double (inorm + residual) stats ----------------
// y1 = inorm(x)+x = x(1+r1) - m*r1 ; mean(y1)=m, var(y1)=(1+r1)^2 var(x)
// y2 = inorm(y1)+y1 = x*A - m*B ;  A=(1+r1)(1+r2), B=r1(1+r2)+r2
// stores {A, m*B} so the apply pass is a single FFMA per element.
__global__ void inorm2_stats_kernel(const float* __restrict__ x, float* __restrict__ stats, int HW) {
    int bc = blockIdx.x;
    const float4* p = (const float4*)(x + (size_t)bc * HW);
    int n4 = HW >> 2;
    __shared__ float red[8];
    __shared__ float mean_s;
    int wid = threadIdx.x >> 5, lid = threadIdx.x & 31;

    float s = 0.f;
    for (int i = threadIdx.x; i < n4; i += 256) {
        float4 v = p[i];
        s += v.x + v.y + v.z + v.w;
    }
    s = warp_sum(s);
    if (lid == 0) red[wid] = s;
    __syncthreads();
    if (threadIdx.x == 0) {
        float tot = 0.f;
#pragma unroll
        for (int i = 0; i < 8; i++) tot += red[i];
        mean_s = tot / (float)HW;
    }
    __syncthreads();

    float m = mean_s;
    float vs = 0.f;
    for (int i = threadIdx.x; i < n4; i += 256) {
        float4 v = p[i];
        float d0 = v.x - m, d1 = v.y - m, d2 = v.z - m, d3 = v.w - m;
        vs += d0*d0 + d1*d1 + d2*d2 + d3*d3;
    }
    vs = warp_sum(vs);
    if (lid == 0) red[wid] = vs;
    __syncthreads();
    if (threadIdx.x == 0) {
        float tot = 0.f;
#pragma unroll
        for (int i = 0; i < 8; i++) tot += red[i];
        float var = tot / (float)HW;
        float r1 = rsqrtf(var + EPS);
        float a1 = 1.f + r1;
        float r2 = rsqrtf(a1 * a1 * var + EPS);
        float A  = a1 * (1.f + r2);
        float B  = r1 * (1.f + r2) + r2;
        stats[2*bc]   = A;
        stats[2*bc+1] = m * B;
    }
}

// apply: MODE 0 -> y = (x-m)*r (first inorm, no residual), using {m, r}
//        MODE 1 -> y = x*A - mB (fused double inorm+residual), using {A, mB}
template <int MODE>
__global__ void inorm_apply_kernel(const float* __restrict__ x, const float* __restrict__ stats,
                                   float* __restrict__ y, int HW, int total4) {
    int i = blockIdx.x * 256 + threadIdx.x;      // float4 index
    if (i >= total4) return;
    int bc = (i << 2) / HW;
    float s0 = stats[2*bc], s1 = stats[2*bc+1];
    float4 v = ((const float4*)x)[i];
    float4 o;
    if constexpr (MODE == 0) {
        o.x = (v.x - s0) * s1; o.y = (v.y - s0) * s1;
        o.z = (v.z - s0) * s1; o.w = (v.w - s0) * s1;
    } else {
        o.x = v.x * s0 - s1; o.y = v.y * s0 - s1;
        o.z = v.z * s0 - s1; o.w = v.w * s0 - s1;
    }
    ((float4*)y)[i] = o;
}

// ---------------- 3x3 conv, pad 1, stride 1 ----------------
// thread: TWO adjacent (y,x)/(y,x+1) pixels, COT output channels.
// Block covers 32x16 pixels with 256 threads. Weights in smem as [ci][k][t].
template <int COT>
__global__ void conv3x3_kernel(const float* __restrict__ in, const float* __restrict__ w,
                               const float* __restrict__ bias, float* __restrict__ out,
                               int Cin, int Cout, int H, int W) {
    extern __shared__ float smw[];   // Cin*9*COT
    int ngrp  = Cout / COT;
    int b     = blockIdx.z / ngrp;
    int obase = (blockIdx.z % ngrp) * COT;

    int tot = Cin * 9 * COT;
    for (int idx = threadIdx.x; idx < tot; idx += 256) {
        int t  = idx % COT;
        int k  = (idx / COT) % 9;
        int ci = idx / (COT * 9);
        smw[idx] = w[((obase + t) * Cin + ci) * 9 + k];
    }
    __syncthreads();

    int x0 = blockIdx.x * 32 + (threadIdx.x & 15) * 2;   // left pixel of pair (even)
    int y0 = blockIdx.y * 16 + (threadIdx.x >> 4);

    // row/col validity & offsets are Cin-invariant: hoist
    bool rok[3]; int roff[3];
    bool cok[4]; int coff[4];
#pragma unroll
    for (int dy = 0; dy < 3; dy++) {
        int yy = y0 + dy - 1;
        rok[dy] = (yy >= 0 && yy < H);
        roff[dy] = rok[dy] ? yy * W : 0;
    }
#pragma unroll
    for (int dx = 0; dx < 4; dx++) {
        int xx = x0 + dx - 1;
        cok[dx] = (xx >= 0 && xx < W);
        coff[dx] = cok[dx] ? xx : 0;
    }

    float acc0[COT], acc1[COT];
#pragma unroll
    for (int t = 0; t < COT; t++) { acc0[t] = bias[obase + t]; acc1[t] = acc0[t]; }

    const float* inb = in + (size_t)b * Cin * H * W;
#pragma unroll 4
    for (int ci = 0; ci < Cin; ci++) {
        const float* ip = inb + (size_t)ci * H * W;
        float v[3][4];
#pragma unroll
        for (int dy = 0; dy < 3; dy++)
#pragma unroll
            for (int dx = 0; dx < 4; dx++)
                v[dy][dx] = (rok[dy] && cok[dx]) ? ip[roff[dy] + coff[dx]] : 0.f;

        const float* wp = smw + ci * 9 * COT;
#pragma unroll
        for (int dy = 0; dy < 3; dy++) {
#pragma unroll
            for (int dx = 0; dx < 3; dx++) {
                int k = dy * 3 + dx;
                float vl = v[dy][dx];       // for pixel x0
                float vr = v[dy][dx + 1];   // for pixel x0+1
                if constexpr (COT == 8) {
                    float4 w0 = *(const float4*)(wp + k*8);
                    float4 w1 = *(const float4*)(wp + k*8 + 4);
                    acc0[0] += vl*w0.x; acc0[1] += vl*w0.y; acc0[2] += vl*w0.z; acc0[3] += vl*w0.w;
                    acc0[4] += vl*w1.x; acc0[5] += vl*w1.y; acc0[6] += vl*w1.z; acc0[7] += vl*w1.w;
                    acc1[0] += vr*w0.x; acc1[1] += vr*w0.y; acc1[2] += vr*w0.z; acc1[3] += vr*w0.w;
                    acc1[4] += vr*w1.x; acc1[5] += vr*w1.y; acc1[6] += vr*w1.z; acc1[7] += vr*w1.w;
                } else {
#pragma unroll
                    for (int t = 0; t < COT; t++) {
                        float wk = wp[k*COT + t];
                        acc0[t] += vl * wk;
                        acc1[t] += vr * wk;
                    }
                }
            }
        }
    }
    size_t o = ((size_t)(b * Cout + obase) * H + y0) * W + x0;
#pragma unroll
    for (int t = 0; t < COT; t++) {
        float2 pr = make_float2(acc0[t], acc1[t]);
        *(float2*)(out + o + (size_t)t * H * W) = pr;   // x0 even -> 8B aligned
    }
}

// ---------------- 1x1 conv + residual (Cin == Cout == Cdim) ----------------
// thread: TWO adjacent pixels, 8 output channels; float2 loads/stores.
__global__ void conv1x1_res_kernel(const float* __restrict__ in, const float* __restrict__ w,
                                   const float* __restrict__ bias, float* __restrict__ out,
                                   int Cdim, int H, int W) {
    __shared__ float smw[128 * 8];
    int ngrp  = Cdim / 8;
    int b     = blockIdx.z / ngrp;
    int obase = (blockIdx.z % ngrp) * 8;
    for (int idx = threadIdx.x; idx < Cdim * 8; idx += 256) {
        int t = idx & 7; int ci = idx >> 3;
        smw[idx] = w[(obase + t) * Cdim + ci];
    }
    __syncthreads();
    int x0 = blockIdx.x * 32 + (threadIdx.x & 15) * 2;   // even
    int y0 = blockIdx.y * 16 + (threadIdx.x >> 4);
    float acc0[8], acc1[8];
#pragma unroll
    for (int t = 0; t < 8; t++) { acc0[t] = bias[obase + t]; acc1[t] = acc0[t]; }
    const float* inb = in + (size_t)b * Cdim * H * W + (size_t)y0 * W + x0;
#pragma unroll 4
    for (int ci = 0; ci < Cdim; ci++) {
        float2 v = *(const float2*)(inb + (size_t)ci * H * W);
        float4 w0 = *(const float4*)(smw + ci*8);
        float4 w1 = *(const float4*)(smw + ci*8 + 4);
        acc0[0] += v.x*w0.x; acc0[1] += v.x*w0.y; acc0[2] += v.x*w0.z; acc0[3] += v.x*w0.w;
        acc0[4] += v.x*w1.x; acc0[5] += v.x*w1.y; acc0[6] += v.x*w1.z; acc0[7] += v.x*w1.w;
        acc1[0] += v.y*w0.x; acc1[1] += v.y*w0.y; acc1[2] += v.y*w0.z; acc1[3] += v.y*w0.w;
        acc1[4] += v.y*w1.x; acc1[5] += v.y*w1.y; acc1[6] += v.y*w1.z; acc1[7] += v.y*w1.w;
    }
#pragma unroll
    for (int t = 0; t < 8; t++) {
        size_t o = ((size_t)(b * Cdim + obase + t) * H + y0) * W + x0;
        float2 rv = *(const float2*)(in + o);
        float2 pr = make_float2(acc0[t] + rv.x, acc1[t] + rv.y);
        *(float2*)(out + o) = pr;
    }
}

// ---------------- PAC gaussian kernel: K[b,k,h,w] = exp(-0.5*sum_c (g_nbr - g_ctr)^2) ----------------
// thread: TWO adjacent pixels share a 3x4 tap window (12 LDG/channel vs 20).
__global__ void pac_k_kernel(const float* __restrict__ g, float* __restrict__ K,
                             int Cg, int H, int W) {
    int x0 = blockIdx.x * 32 + (threadIdx.x & 15) * 2;   // even
    int y0 = blockIdx.y * 16 + (threadIdx.x >> 4);
    int b  = blockIdx.z;

    bool rok[3]; int roff[3];
    bool cok[4]; int coff[4];
#pragma unroll
    for (int dy = 0; dy < 3; dy++) {
        int yy = y0 + dy - 1;
        rok[dy] = (yy >= 0 && yy < H);
        roff[dy] = rok[dy] ? yy * W : 0;
    }
#pragma unroll
    for (int dx = 0; dx < 4; dx++) {
        int xx = x0 + dx - 1;
        cok[dx] = (xx >= 0 && xx < W);
        coff[dx] = cok[dx] ? xx : 0;
    }

    float acc0[9], acc1[9];
#pragma unroll
    for (int k = 0; k < 9; k++) { acc0[k] = 0.f; acc1[k] = 0.f; }

    const float* gb = g + (size_t)b * Cg * H * W;
#pragma unroll 2
    for (int c = 0; c < Cg; c++) {
        const float* gp = gb + (size_t)c * H * W;
        float v[3][4];
#pragma unroll
        for (int dy = 0; dy < 3; dy++)
#pragma unroll
            for (int dx = 0; dx < 4; dx++)
                v[dy][dx] = (rok[dy] && cok[dx]) ? gp[roff[dy] + coff[dx]] : 0.f;
        float ctr0 = v[1][1];      // center of left pixel (always valid)
        float ctr1 = v[1][2];      // center of right pixel (always valid)
#pragma unroll
        for (int dy = 0; dy < 3; dy++) {
#pragma unroll
            for (int dx = 0; dx < 3; dx++) {
                int k = dy * 3 + dx;
                float d0 = v[dy][dx]     - ctr0;   // invalid tap reads 0 -> d=-ctr (zero-pad semantics)
                float d1 = v[dy][dx + 1] - ctr1;
                acc0[k] += d0 * d0;
                acc1[k] += d1 * d1;
            }
        }
    }
#pragma unroll
    for (int k = 0; k < 9; k++) {
        float2 pr = make_float2(expf(-0.5f * acc0[k]), expf(-0.5f * acc1[k]));
        *(float2*)(K + ((size_t)(b * 9 + k) * H + y0) * W + x0) = pr;
    }
}

// ---------------- PacConvTranspose2d (k=3, s=2, p=1, out_pad=1) ----------------
// Each thread owns a 2x2 output quad (rows 2r,2r+1 / cols 2s,2s+1) x COT out-channels.
// Each of the 9 taps is valid for exactly one quad pixel (parity structure) -> no divergence.
template <int COT>
__global__ void pacconvT_kernel(const float* __restrict__ x, const float* __restrict__ K,
                                const float* __restrict__ w, const float* __restrict__ bias,
                                float* __restrict__ out, int Cin, int Cout, int Hin, int Win) {
    extern __shared__ float smw[];    // [k][c][t] : 9*Cin*COT
    int Ho = 2 * Hin, Wo = 2 * Win;
    int ngrp  = Cout / COT;
    int b     = blockIdx.z / ngrp;
    int obase = (blockIdx.z % ngrp) * COT;

    int tot = 9 * Cin * COT;
    for (int idx = threadIdx.x; idx < tot; idx += 256) {
        int t = idx % COT;
        int c = (idx / COT) % Cin;
        int k = idx / (COT * Cin);
        smw[idx] = w[((c * Cout) + obase + t) * 9 + k];  // W layout (Cin,Cout,3,3), no flip
    }
    __syncthreads();

    int s = blockIdx.x * 16 + (threadIdx.x & 15);   // quad col
    int r = blockIdx.y * 16 + (threadIdx.x >> 4);   // quad row

    float acc[2][2][COT];
#pragma unroll
    for (int pi = 0; pi < 2; pi++)
#pragma unroll
        for (int pj = 0; pj < 2; pj++)
#pragma unroll
            for (int t = 0; t < COT; t++) acc[pi][pj][t] = bias[obase + t];

    const float* xb = x + (size_t)b * Cin * Hin * Win;
    const float* Kb = K + (size_t)b * 9 * Ho * Wo;

#pragma unroll
    for (int i = 0; i < 3; i++) {
        int yy = r + (i == 2 ? 1 : 0);
        if (yy >= Hin) continue;
        int pi = (i == 1) ? 0 : 1;
#pragma unroll
        for (int j = 0; j < 3; j++) {
            int xx = s + (j == 2 ? 1 : 0);
            if (xx >= Win) continue;
            int pj = (j == 1) ? 0 : 1;
            int k = i * 3 + j;

            float cs[COT];
#pragma unroll
            for (int t = 0; t < COT; t++) cs[t] = 0.f;
            const float* wp = smw + (size_t)k * Cin * COT;
            const float* xp = xb + (size_t)yy * Win + xx;
#pragma unroll 4
            for (int c = 0; c < Cin; c++) {
                float v = xp[(size_t)c * Hin * Win];
                if constexpr (COT == 8) {
                    float4 w0 = *(const float4*)(wp + c*8);
                    float4 w1 = *(const float4*)(wp + c*8 + 4);
                    cs[0] += v*w0.x; cs[1] += v*w0.y; cs[2] += v*w0.z; cs[3] += v*w0.w;
                    cs[4] += v*w1.x; cs[5] += v*w1.y; cs[6] += v*w1.z; cs[7] += v*w1.w;
                } else {
#pragma unroll
                    for (int t = 0; t < COT; t++) cs[t] += v * wp[c*COT + t];
                }
            }
            float Kv = Kb[((size_t)k * Ho + (2*r + pi)) * Wo + (2*s + pj)];
#pragma unroll
            for (int t = 0; t < COT; t++) acc[pi][pj][t] += Kv * cs[t];
        }
    }

#pragma unroll
    for (int pi = 0; pi < 2; pi++)
#pragma unroll
        for (int pj = 0; pj < 2; pj++)
#pragma unroll
            for (int t = 0; t < COT; t++)
                out[((size_t)(b * Cout + obase + t) * Ho + (2*r + pi)) * Wo + (2*s + pj)] =
                    acc[pi][pj][t];
}

// ---------------- launch ----------------
extern "C" void kernel_launch(void* const* d_in, const int* in_sizes, int n_in,
                              void* d_out, int out_size) {
    (void)in_sizes; (void)n_in; (void)out_size;
    const float* x      = (const float*)d_in[0];
    const float* ef2    = (const float*)d_in[1];
    const float* ef1    = (const float*)d_in[2];
    const float* W_down = (const float*)d_in[3];
    const float* b_down = (const float*)d_in[4];
    const float* W_mid  = (const float*)d_in[5];
    const float* b_mid  = (const float*)d_in[6];
    const float* W_adj2 = (const float*)d_in[7];
    const float* b_adj2 = (const float*)d_in[8];
    const float* W_adj1 = (const float*)d_in[9];
    const float* b_adj1 = (const float*)d_in[10];
    const float* W16    = (const float*)d_in[11];
    const float* b16    = (const float*)d_in[12];
    const float* W20    = (const float*)d_in[13];
    const float* b20    = (const float*)d_in[14];
    const float* W24    = (const float*)d_in[15];
    const float* b24    = (const float*)d_in[16];
    float* out = (float*)d_out;

    float *bufA, *bufB, *bufC, *bufG2, *bufK2, *bufX16, *bufG1, *bufK1, *bufX20, *stats;
    cudaGetSymbolAddress((void**)&bufA,  g_bufA);
    cudaGetSymbolAddress((void**)&bufB,  g_bufB);
    cudaGetSymbolAddress((void**)&bufC,  g_bufC);
    cudaGetSymbolAddress((void**)&bufG2, g_bufG2);
    cudaGetSymbolAddress((void**)&bufK2, g_bufK2);
    cudaGetSymbolAddress((void**)&bufX16, g_bufX16);
    cudaGetSymbolAddress((void**)&bufG1, g_bufG1);
    cudaGetSymbolAddress((void**)&bufK1, g_bufK1);
    cudaGetSymbolAddress((void**)&bufX20, g_bufX20);
    cudaGetSymbolAddress((void**)&stats, g_stats);

    // conv_down needs 72 KB dynamic smem
    cudaFuncSetAttribute(conv3x3_kernel<8>, cudaFuncAttributeMaxDynamicSharedMemorySize,
                         8 * 256 * 9 * 4);

    // 1) inorm(x) -> bufA
    inorm_stats_kernel<<<2*256, 256>>>(x, stats, 64*64);
    inorm_apply_kernel<0><<<(2*256*64*64/4 + 255)/256, 256>>>(x, stats, bufA, 64*64, 2*256*64*64/4);

    // 2) conv_down 256->128 @64x64 -> bufB  (blocks cover 32x16 px)
    conv3x3_kernel<8><<<dim3(2,4,2*16), 256, 8*256*9*4>>>(bufA, W_down, b_down, bufB, 256, 128, 64, 64);

    // 3) mid 1x1 + residual -> bufC  (blocks cover 32x16 px)
    conv1x1_res_kernel<<<dim3(2,4,2*16), 256>>>(bufB, W_mid, b_mid, bufC, 128, 64, 64);

    // 4) adjust_ef_lv2: 64->128 @128x128 -> bufG2
    conv3x3_kernel<8><<<dim3(4,8,2*16), 256, 8*64*9*4>>>(ef2, W_adj2, b_adj2, bufG2, 64, 128, 128, 128);

    // 5) pac kernel lvl2 -> bufK2  (blocks cover 32x16 px)
    pac_k_kernel<<<dim3(4,8,2), 256>>>(bufG2, bufK2, 128, 128, 128);

    // 6) layer16 pacconvT 128->64, 64x64 -> 128x128  (COT=8: Cout/8 = 8 groups)
    pacconvT_kernel<8><<<dim3(4,4,2*8), 256, 9*128*8*4>>>(bufC, bufK2, W16, b16, bufX16, 128, 64, 64, 64);

    // 7) fused double (inorm + residual), in place
    inorm2_stats_kernel<<<2*64, 256>>>(bufX16, stats, 128*128);
    inorm_apply_kernel<1><<<(2*64*128*128/4 + 255)/256, 256>>>(bufX16, stats, bufX16, 128*128, 2*64*128*128/4);

    // 8) adjust_ef_lv1: 32->64 @256x256 -> bufG1
    conv3x3_kernel<8><<<dim3(8,16,2*8), 256, 8*32*9*4>>>(ef1, W_adj1, b_adj1, bufG1, 32, 64, 256, 256);

    // 9) pac kernel lvl1 -> bufK1  (blocks cover 32x16 px)
    pac_k_kernel<<<dim3(8,16,2), 256>>>(bufG1, bufK1, 64, 256, 256);

    // 10) layer20 pacconvT 64->32, 128x128 -> 256x256  (COT=8: Cout/8 = 4 groups)
    pacconvT_kernel<8><<<dim3(8,8,2*4), 256, 9*64*8*4>>>(bufX16, bufK1, W20, b20, bufX20, 64, 32, 128, 128);

    // 11) fused double (inorm + residual), in place
    inorm2_stats_kernel<<<2*32, 256>>>(bufX20, stats, 256*256);
    inorm_apply_kernel<1><<<(2*32*256*256/4 + 255)/256, 256>>>(bufX20, stats, bufX20, 256*256, 2*32*256*256/4);

    // 12) final conv 32->3 @256x256 -> out
    conv3x3_kernel<3><<<dim3(8,16,2), 256, 32*9*3*4>>>(bufX20, W24, b24, out, 32, 3, 256, 256);
}